// round 15
// baseline (speedup 1.0000x reference)
#include <cuda_runtime.h>
#include <cuda_bf16.h>

#define MCTA 16
#define NCTAS 128
#define NTHREADS 512
#define NWARPS 16
#define T_STEPS 128
#define KS8 8                 // int8 k32-steps covering cols 0..255
#define ACT8_STRIDE 272       // bytes per act8 row
#define ACTT_STRIDE 24        // bf16 elems per tail row (48B)
#define INVS (1.0f / 258064.0f)   // 1/(2032*127)

// ---------------------------------------------------------------------------
// Weights:
//  g_W8:    int8 main fragments, [tile(160)][ks8(8)][lane] uint2
//           (.x bytes = k 4(lane&3)+0..3, .y = +16; k = ks*32 + ...)
//  g_Wtail: bf16 tail fragments (cols 256..271), [tile(160)][lane] uint2
//  Tile map (16 warps): tile<32: GEMM1 (Wm0), warp w owns 2w,2w+1.
//  tile>=32: q=tile-32, w=q/8, j=q%8: j<6 -> GEMM2 tg=6w+j (Wf10|Wf20|Wh0);
//            j>=6 -> GEMM3 (Wm1) n-tile 2w+(j-6).
// ---------------------------------------------------------------------------
__device__ uint2 g_W8[160 * 8 * 32];
__device__ uint2 g_Wtail[160 * 32];
__device__ float4 g_smallW4[768];

#define W8_WORDS (160 * 8 * 32 * 2)
#define WT_WORDS (160 * 32 * 2)

// ---------------------------------------------------------------------------
// Tail column layout (bf16 actT, cols 256..271 of padded K):
//   actT col 0..1: meas/60   col 2..5: s/60   col 6..15: zero
// Tail row remap (k in 256..271):
//   type0 (Wm0,Wf10,Wf20): 258..261 -> k-2, else zero
//   type1 (Wh0): 256,257 -> k+4 ; 258..261 -> k-2 ; else zero
//   type2 (Wm1): k<262 -> k ; else zero
// ---------------------------------------------------------------------------
__global__ void prepack_kernel(
    const float* __restrict__ Wm0, const float* __restrict__ Wf10,
    const float* __restrict__ Wf20, const float* __restrict__ Wh0,
    const float* __restrict__ Wm1, const float* __restrict__ Wf11,
    const float* __restrict__ Wf21, const float* __restrict__ Wh1)
{
    int idx = blockIdx.x * blockDim.x + threadIdx.x;
    if (idx < W8_WORDS) {
        int r    = idx & 1;
        int lane = (idx >> 1) & 31;
        int ks   = (idx >> 6) & 7;
        int tile = idx >> 9;
        int kbase = ks * 32 + 4 * (lane & 3) + r * 16;
        const float* W; int ncol;
        if (tile < 32) {
            W = Wm0; ncol = tile * 8 + (lane >> 2);
        } else {
            int q = tile - 32, wq = q >> 3, j = q & 7;
            if (j < 6) {
                int n2 = (wq * 6 + j) * 8 + (lane >> 2);
                if (n2 < 256)      { W = Wf10; ncol = n2; }
                else if (n2 < 512) { W = Wf20; ncol = n2 - 256; }
                else               { W = Wh0;  ncol = n2 - 512; }
            } else {
                W = Wm1; ncol = (wq * 2 + (j - 6)) * 8 + (lane >> 2);
            }
        }
        unsigned pk = 0;
#pragma unroll
        for (int jb = 0; jb < 4; jb++) {
            float v = W[(size_t)(kbase + jb) * 256 + ncol];
            int q8 = __float2int_rn(v * 2032.0f);
            q8 = max(-127, min(127, q8));
            pk |= ((unsigned)(q8 & 0xff)) << (8 * jb);
        }
        reinterpret_cast<unsigned*>(g_W8)[idx] = pk;
    } else if (idx < W8_WORDS + WT_WORDS) {
        int idx2 = idx - W8_WORDS;
        int r    = idx2 & 1;
        int lane = (idx2 >> 1) & 31;
        int tile = idx2 >> 6;
        int kk = 256 + (lane & 3) * 2 + r * 8;
        const float* W; int type; int ncol;
        if (tile < 32) {
            W = Wm0; type = 0; ncol = tile * 8 + (lane >> 2);
        } else {
            int q = tile - 32, wq = q >> 3, j = q & 7;
            if (j < 6) {
                int n2 = (wq * 6 + j) * 8 + (lane >> 2);
                if (n2 < 256)      { W = Wf10; type = 0; ncol = n2; }
                else if (n2 < 512) { W = Wf20; type = 0; ncol = n2 - 256; }
                else               { W = Wh0;  type = 1; ncol = n2 - 512; }
            } else {
                W = Wm1; type = 2; ncol = (wq * 2 + (j - 6)) * 8 + (lane >> 2);
            }
        }
        auto srcrow = [&](int k) -> int {
            if (type == 0) return (k >= 258 && k < 262) ? k - 2 : -1;
            if (type == 1) return k < 258 ? k + 4 : (k < 262 ? k - 2 : -1);
            return k < 262 ? k : -1;
        };
        int s0 = srcrow(kk), s1 = srcrow(kk + 1);
        float v0 = (s0 >= 0) ? W[(size_t)s0 * 256 + ncol] : 0.f;
        float v1 = (s1 >= 0) ? W[(size_t)s1 * 256 + ncol] : 0.f;
        __nv_bfloat162 p;
        p.x = __float2bfloat16(v0);
        p.y = __float2bfloat16(v1);
        reinterpret_cast<unsigned*>(g_Wtail)[idx2] =
            *reinterpret_cast<unsigned*>(&p);
    } else if (idx < W8_WORDS + WT_WORDS + 768) {
        int j = idx - W8_WORDS - WT_WORDS;
        float4 v = make_float4(0.f, 0.f, 0.f, 0.f);
        if (j < 256)      { v.x = Wf11[j * 2];        v.y = Wf11[j * 2 + 1]; }
        else if (j < 512) { int q = j - 256;
                            v.x = Wf21[q * 4]; v.y = Wf21[q * 4 + 1];
                            v.z = Wf21[q * 4 + 2]; v.w = Wf21[q * 4 + 3]; }
        else              { int q = j - 512;
                            v.x = Wh1[q * 2];  v.y = Wh1[q * 2 + 1]; }
        g_smallW4[j] = v;
    }
}

// ---------------------------------------------------------------------------
__device__ __forceinline__ void mma16816(float* d, const unsigned* a, uint2 b) {
    asm volatile(
        "mma.sync.aligned.m16n8k16.row.col.f32.bf16.bf16.f32 "
        "{%0,%1,%2,%3}, {%4,%5,%6,%7}, {%8,%9}, {%0,%1,%2,%3};\n"
        : "+f"(d[0]), "+f"(d[1]), "+f"(d[2]), "+f"(d[3])
        : "r"(a[0]), "r"(a[1]), "r"(a[2]), "r"(a[3]), "r"(b.x), "r"(b.y));
}
__device__ __forceinline__ void mma8(int* d, const unsigned* a, uint2 b) {
    asm volatile(
        "mma.sync.aligned.m16n8k32.row.col.s32.s8.s8.s32 "
        "{%0,%1,%2,%3}, {%4,%5,%6,%7}, {%8,%9}, {%0,%1,%2,%3};\n"
        : "+r"(d[0]), "+r"(d[1]), "+r"(d[2]), "+r"(d[3])
        : "r"(a[0]), "r"(a[1]), "r"(a[2]), "r"(a[3]), "r"(b.x), "r"(b.y));
}
__device__ __forceinline__ void ldmA(unsigned* a, unsigned addr) {
    asm volatile(
        "ldmatrix.sync.aligned.m8n8.x4.shared.b16 {%0,%1,%2,%3}, [%4];\n"
        : "=r"(a[0]), "=r"(a[1]), "=r"(a[2]), "=r"(a[3]) : "r"(addr));
}
__device__ __forceinline__ float tanha(float x) {
    float y; asm("tanh.approx.f32 %0, %1;" : "=f"(y) : "f"(x)); return y;
}
__device__ __forceinline__ unsigned packbf2(float a, float b) {
    __nv_bfloat162 h;
    h.x = __float2bfloat16(a);
    h.y = __float2bfloat16(b);
    return *reinterpret_cast<unsigned*>(&h);
}

// tanh + int8 quantize (scale 127) + store 2 bytes per row into act8
__device__ __forceinline__ void write_act8_tanh(int ntile, int cbase, int row0,
        const float (&D)[4], const float* __restrict__ bias,
        char (*a8)[ACT8_STRIDE]) {
    int col = ntile * 8 + cbase;
    float bv0 = bias[col], bv1 = bias[col + 1];
    int q0 = __float2int_rn(tanha(D[0] + bv0) * 127.f);
    int q1 = __float2int_rn(tanha(D[1] + bv1) * 127.f);
    int q2 = __float2int_rn(tanha(D[2] + bv0) * 127.f);
    int q3 = __float2int_rn(tanha(D[3] + bv1) * 127.f);
    *reinterpret_cast<unsigned short*>(&a8[row0][col]) =
        (unsigned short)((q0 & 0xff) | ((q1 & 0xff) << 8));
    *reinterpret_cast<unsigned short*>(&a8[row0 + 8][col]) =
        (unsigned short)((q2 & 0xff) | ((q3 & 0xff) << 8));
}

__device__ __forceinline__ void g2_epilogue(int tg, int cbase,
        const float (&D)[4], const float* __restrict__ bias2s,
        const float4* __restrict__ smallWs, float (&o)[2][8]) {
    int col = tg * 8 + cbase;
    int seg = tg >> 5;  // 0: Wf11 (d), 1: Wf21 (pv), 2: Wh1 (hv)
    float bb0 = bias2s[col], bb1 = bias2s[col + 1];
    float4 w0 = smallWs[col];
    float4 w1 = smallWs[col + 1];
    int ob = (seg == 0) ? 0 : ((seg == 1) ? 2 : 6);
    float h0 = tanha(D[0] + bb0);
    float h1 = tanha(D[1] + bb1);
    float h2 = tanha(D[2] + bb0);
    float h3 = tanha(D[3] + bb1);
    o[0][ob + 0] += h0 * w0.x + h1 * w1.x;
    o[0][ob + 1] += h0 * w0.y + h1 * w1.y;
    o[1][ob + 0] += h2 * w0.x + h3 * w1.x;
    o[1][ob + 1] += h2 * w0.y + h3 * w1.y;
    if (seg == 1) {
        o[0][ob + 2] += h0 * w0.z + h1 * w1.z;
        o[0][ob + 3] += h0 * w0.w + h1 * w1.w;
        o[1][ob + 2] += h2 * w0.z + h3 * w1.z;
        o[1][ob + 3] += h2 * w0.w + h3 * w1.w;
    }
}

// ---------------------------------------------------------------------------
// Main persistent kernel: 128 CTAs x 512 threads, 16 batch rows per CTA.
// R13 structure; GEMM main parts in INT8 (8 k32-steps), tails (cols 256..271:
// meas/60, s/60) in bf16 via one k16 MMA per tile.
// ---------------------------------------------------------------------------
__global__ void __launch_bounds__(NTHREADS, 1) egbrnn_main(
    const float* __restrict__ x, const float* __restrict__ target,
    const float* __restrict__ c0,
    const float* __restrict__ bm0, const float* __restrict__ bm1,
    const float* __restrict__ bf10, const float* __restrict__ bf11,
    const float* __restrict__ bf20, const float* __restrict__ bf21,
    const float* __restrict__ bh0, const float* __restrict__ bh1,
    float* __restrict__ out)
{
    __shared__ __align__(16) char act8[MCTA][ACT8_STRIDE];
    __shared__ __align__(16) __nv_bfloat16 actT[MCTA][ACTT_STRIDE];
    __shared__ float sS[MCTA][4];
    __shared__ float Pm[MCTA][16];
    __shared__ __align__(16) float part[NWARPS][MCTA][12];
    __shared__ float bm0s[256], bm1s[256], bias2s[768], biasSs[8];
    __shared__ __align__(16) float4 smallWs[768];

    const int tid = threadIdx.x;
    const int w = tid >> 5, lane = tid & 31;
    const int b0 = blockIdx.x * MCTA;
    const int row0 = lane >> 2;
    const int cbase = (lane & 3) * 2;

    // ---- one-time shared init ----
    if (tid < 256) { bm0s[tid] = bm0[tid]; bm1s[tid] = bm1[tid]; }
    for (int i = tid; i < 768; i += NTHREADS) {
        bias2s[i] = (i < 256) ? bf10[i] : (i < 512 ? bf20[i - 256] : bh0[i - 512]);
        smallWs[i] = g_smallW4[i];
    }
    if (tid < 8)
        biasSs[tid] = (tid < 2) ? bf11[tid] : (tid < 6 ? bf21[tid - 2] : bh1[tid - 6]);
    for (int i = tid; i < MCTA * ACTT_STRIDE; i += NTHREADS) {  // zero tail buf
        int r = i / ACTT_STRIDE, c = i % ACTT_STRIDE;
        actT[r][c] = __float2bfloat16(0.f);
    }
    for (int i = tid; i < MCTA * 256; i += NTHREADS) {  // act8 = quant(c0)
        int r = i >> 8, j = i & 255;
        float v = c0[(size_t)(b0 + r) * 256 + j];
        int q = __float2int_rn(v * 127.f);
        q = max(-127, min(127, q));
        act8[r][j] = (char)q;
    }
    __syncthreads();
    if (tid < MCTA) {
        int r = tid;
        float4 tg = *reinterpret_cast<const float4*>(
            &target[((size_t)(b0 + r) * T_STEPS) * 4]);
        sS[r][0] = tg.x; sS[r][1] = tg.y; sS[r][2] = tg.z; sS[r][3] = tg.w;
#pragma unroll
        for (int i = 0; i < 16; i++) Pm[r][i] = (i % 5 == 0) ? 1.f : 0.f;
        // actT cols 2..5 = s0/60 (cols 0..1 = m2, zero until P2)
        *reinterpret_cast<unsigned*>(&actT[r][2]) =
            packbf2(tg.x * (1.f / 60.f), tg.y * (1.f / 60.f));
        *reinterpret_cast<unsigned*>(&actT[r][4]) =
            packbf2(tg.z * (1.f / 60.f), tg.w * (1.f / 60.f));
    }
    __syncthreads();

    const unsigned ab8 = (unsigned)__cvta_generic_to_shared(
        &act8[lane & 15][(lane >> 4) * 16]);
    const unsigned abT = (unsigned)__cvta_generic_to_shared(
        &actT[lane & 15][(lane >> 4) * 8]);
    const uint2* wG18 = g_W8 + (2 * w) * (KS8 * 32) + lane;
    const uint2* wP38 = g_W8 + (32 + 8 * w) * (KS8 * 32) + lane;
    const uint2* wTg1 = g_Wtail + (2 * w) * 32 + lane;
    const uint2* wTp3 = g_Wtail + (32 + 8 * w) * 32 + lane;

    float2 xcur, xnxt;   // meas prefetch (meaningful for tid<16 only)
    if (tid < MCTA)
        xcur = *reinterpret_cast<const float2*>(
            &x[((size_t)(b0 + tid)) * T_STEPS * 2]);

    for (int t = 0; t < T_STEPS; t++) {
        // ---- P1: GEMM1 = int8 main (8 ksteps) + bf16 tail (old sn) ----
        int D1i[2][4];
#pragma unroll
        for (int i = 0; i < 2; i++)
            D1i[i][0] = D1i[i][1] = D1i[i][2] = D1i[i][3] = 0;
        {
            unsigned a[2][4];
            uint2 b1[2][2];
            b1[0][0] = wG18[0];
            b1[1][0] = wG18[KS8 * 32];
            b1[0][1] = wG18[32];
            b1[1][1] = wG18[(KS8 + 1) * 32];
            ldmA(a[0], ab8);
#pragma unroll
            for (int ks = 0; ks < KS8; ks++) {
                if (ks + 1 < KS8)
                    ldmA(a[(ks + 1) & 1], ab8 + (unsigned)(ks + 1) * 32u);
                mma8(D1i[0], a[ks & 1], b1[0][ks & 1]);
                mma8(D1i[1], a[ks & 1], b1[1][ks & 1]);
                if (ks + 2 < KS8) {
                    b1[0][ks & 1] = wG18[(0 * KS8 + ks + 2) * 32];
                    b1[1][ks & 1] = wG18[(1 * KS8 + ks + 2) * 32];
                }
            }
        }
        float D1[2][4];
        {
            uint2 t0 = wTg1[0], t1 = wTg1[32];
            unsigned at[4];
            ldmA(at, abT);
#pragma unroll
            for (int i = 0; i < 2; i++)
#pragma unroll
                for (int q = 0; q < 4; q++)
                    D1[i][q] = (float)D1i[i][q] * INVS;
            mma16816(D1[0], at, t0);
            mma16816(D1[1], at, t1);
        }
        __syncthreads();

        // ---- P2: write cu (int8); m2 to actT; tG3 tails; next-meas ----
        write_act8_tanh(2 * w,     cbase, row0, D1[0], bm0s, act8);
        write_act8_tanh(2 * w + 1, cbase, row0, D1[1], bm0s, act8);
        uint2 tG3[2];
        tG3[0] = wTp3[6 * 32];
        tG3[1] = wTp3[7 * 32];
        if (tid < MCTA) {
            *reinterpret_cast<unsigned*>(&actT[tid][0]) =
                packbf2(xcur.x * (1.f / 60.f), xcur.y * (1.f / 60.f));
            int tn = (t + 1 < T_STEPS) ? t + 1 : t;
            xnxt = *reinterpret_cast<const float2*>(
                &x[(((size_t)(b0 + tid)) * T_STEPS + tn) * 2]);
        }
        __syncthreads();

        // ---- P3: int8 main for 8 tiles (6 G2 + 2 G3), then G2 bf16 tails ----
        int D2i[8][4];
#pragma unroll
        for (int i = 0; i < 8; i++)
            D2i[i][0] = D2i[i][1] = D2i[i][2] = D2i[i][3] = 0;
        {
            unsigned a[2][4];
            uint2 b[8][2];
#pragma unroll
            for (int i = 0; i < 8; i++) {
                b[i][0] = wP38[(i * KS8 + 0) * 32];
                b[i][1] = wP38[(i * KS8 + 1) * 32];
            }
            ldmA(a[0], ab8);
#pragma unroll
            for (int ks = 0; ks < KS8; ks++) {
                if (ks + 1 < KS8)
                    ldmA(a[(ks + 1) & 1], ab8 + (unsigned)(ks + 1) * 32u);
#pragma unroll
                for (int i = 0; i < 8; i++) {
                    mma8(D2i[i], a[ks & 1], b[i][ks & 1]);
                    if (ks + 2 < KS8)
                        b[i][ks & 1] = wP38[(i * KS8 + ks + 2) * 32];
                }
            }
        }
        float o[2][8];
#pragma unroll
        for (int s = 0; s < 2; s++)
#pragma unroll
            for (int k = 0; k < 8; k++) o[s][k] = 0.f;
        {
            unsigned at[4];
            ldmA(at, abT);    // current m2 + OLD sn (pre-update) — correct
#pragma unroll
            for (int j = 0; j < 6; j++) {
                uint2 tb = wTp3[j * 32];
                float Df[4];
#pragma unroll
                for (int q = 0; q < 4; q++)
                    Df[q] = (float)D2i[j][q] * INVS;
                mma16816(Df, at, tb);
                g2_epilogue(6 * w + j, cbase, Df, bias2s, smallWs, o);
            }
        }
#pragma unroll
        for (int s = 0; s < 2; s++)
#pragma unroll
            for (int k = 0; k < 8; k++) {
                o[s][k] += __shfl_xor_sync(0xffffffffu, o[s][k], 1);
                o[s][k] += __shfl_xor_sync(0xffffffffu, o[s][k], 2);
            }
        if ((lane & 3) == 0) {
            float4* p0 = reinterpret_cast<float4*>(part[w][row0]);
            float4* p1 = reinterpret_cast<float4*>(part[w][row0 + 8]);
            p0[0] = make_float4(o[0][0], o[0][1], o[0][2], o[0][3]);
            p0[1] = make_float4(o[0][4], o[0][5], o[0][6], o[0][7]);
            p1[0] = make_float4(o[1][0], o[1][1], o[1][2], o[1][3]);
            p1[1] = make_float4(o[1][4], o[1][5], o[1][6], o[1][7]);
        }
        __syncthreads();

        // ---- P4: per-row Kalman update (fp32), tid<16 ----
        if (tid < MCTA) {
            const int r = tid;
            float sm[8];
#pragma unroll
            for (int k = 0; k < 8; k++) sm[k] = biasSs[k];
#pragma unroll
            for (int ww = 0; ww < NWARPS; ww++) {
                const float4* pp = reinterpret_cast<const float4*>(part[ww][r]);
                float4 v0 = pp[0], v1 = pp[1];
                sm[0] += v0.x; sm[1] += v0.y; sm[2] += v0.z; sm[3] += v0.w;
                sm[4] += v1.x; sm[5] += v1.y; sm[6] += v1.z; sm[7] += v1.w;
            }
            const float d0 = sm[0], d1 = sm[1];
            const float pv[4] = {sm[2], sm[3], sm[4], sm[5]};
            const float hv0 = sm[6], hv1 = sm[7];
            float s0 = sS[r][0], s1 = sS[r][1], s2 = sS[r][2], s3 = sS[r][3];
            float sp[4];
            sp[0] = s0 + s2 + 0.5f * d0;
            sp[1] = s1 + s3 + 0.5f * d1;
            sp[2] = s2 + d0;
            sp[3] = s3 + d1;
            float P[4][4];
#pragma unroll
            for (int i = 0; i < 4; i++)
#pragma unroll
                for (int j = 0; j < 4; j++) P[i][j] = Pm[r][i * 4 + j];
            float FP[4][4], Pp[4][4];
#pragma unroll
            for (int j = 0; j < 4; j++) {
                FP[0][j] = P[0][j] + P[2][j];
                FP[1][j] = P[1][j] + P[3][j];
                FP[2][j] = P[2][j];
                FP[3][j] = P[3][j];
            }
#pragma unroll
            for (int i = 0; i < 4; i++) {
                Pp[i][0] = FP[i][0] + FP[i][2];
                Pp[i][1] = FP[i][1] + FP[i][3];
                Pp[i][2] = FP[i][2];
                Pp[i][3] = FP[i][3];
            }
#pragma unroll
            for (int i = 0; i < 4; i++)
#pragma unroll
                for (int j = 0; j < 4; j++) Pp[i][j] += pv[i] * pv[j];
#pragma unroll
            for (int i = 0; i < 4; i++) Pp[i][i] += 0.01f;
            float m0 = xcur.x, m1 = xcur.y;
            float in0 = m0 - sp[0], in1 = m1 - sp[1];
            float S00 = Pp[0][0] + hv0 * hv0 + 1.f;
            float S01 = Pp[0][1] + hv0 * hv1;
            float S10 = Pp[1][0] + hv1 * hv0;
            float S11 = Pp[1][1] + hv1 * hv1 + 1.f;
            float inv = 1.0f / (S00 * S11 - S01 * S10);
            float K[4][2], KS[4][2], su[4];
#pragma unroll
            for (int i = 0; i < 4; i++) {
                K[i][0] = (Pp[i][0] * S11 - Pp[i][1] * S10) * inv;
                K[i][1] = (Pp[i][1] * S00 - Pp[i][0] * S01) * inv;
                su[i] = sp[i] + K[i][0] * in0 + K[i][1] * in1;
                KS[i][0] = K[i][0] * S00 + K[i][1] * S10;
                KS[i][1] = K[i][0] * S01 + K[i][1] * S11;
            }
#pragma unroll
            for (int i = 0; i < 4; i++)
#pragma unroll
                for (int j = 0; j < 4; j++)
                    Pm[r][i * 4 + j] =
                        Pp[i][j] - KS[i][0] * K[j][0] - KS[i][1] * K[j][1];
            sS[r][0] = su[0]; sS[r][1] = su[1];
            sS[r][2] = su[2]; sS[r][3] = su[3];
            *reinterpret_cast<float4*>(
                &out[(((size_t)(b0 + r)) * T_STEPS + t) * 4]) =
                make_float4(su[0], su[1], su[2], su[3]);
            // new sn = su/60 into actT (read by P5 now and P1/P3 next step)
            *reinterpret_cast<unsigned*>(&actT[r][2]) =
                packbf2(su[0] * (1.f / 60.f), su[1] * (1.f / 60.f));
            *reinterpret_cast<unsigned*>(&actT[r][4]) =
                packbf2(su[2] * (1.f / 60.f), su[3] * (1.f / 60.f));
            xcur = xnxt;
        }
        __syncthreads();

        // ---- P5: GEMM3 = int8 main (from P3) + bf16 tail (m2, NEW sn);
        //      writes c_new int8 to act8 cols 0..255 (tail reads disjoint) ----
        {
            float D3[2][4];
#pragma unroll
            for (int q = 0; q < 4; q++) {
                D3[0][q] = (float)D2i[6][q] * INVS;
                D3[1][q] = (float)D2i[7][q] * INVS;
            }
            unsigned at[4];
            ldmA(at, abT);
            mma16816(D3[0], at, tG3[0]);
            mma16816(D3[1], at, tG3[1]);
            write_act8_tanh(2 * w,     cbase, row0, D3[0], bm1s, act8);
            write_act8_tanh(2 * w + 1, cbase, row0, D3[1], bm1s, act8);
        }
        __syncthreads();
    }
}

// ---------------------------------------------------------------------------
extern "C" void kernel_launch(void* const* d_in, const int* in_sizes, int n_in,
                              void* d_out, int out_size)
{
    const float* x    = (const float*)d_in[0];
    const float* targ = (const float*)d_in[1];
    const float* c0   = (const float*)d_in[2];
    const float* Wm0  = (const float*)d_in[3];
    const float* bm0  = (const float*)d_in[4];
    const float* Wm1  = (const float*)d_in[5];
    const float* bm1  = (const float*)d_in[6];
    const float* Wf10 = (const float*)d_in[7];
    const float* bf10 = (const float*)d_in[8];
    const float* Wf11 = (const float*)d_in[9];
    const float* bf11 = (const float*)d_in[10];
    const float* Wf20 = (const float*)d_in[11];
    const float* bf20 = (const float*)d_in[12];
    const float* Wf21 = (const float*)d_in[13];
    const float* bf21 = (const float*)d_in[14];
    const float* Wh0  = (const float*)d_in[15];
    const float* bh0  = (const float*)d_in[16];
    const float* Wh1  = (const float*)d_in[17];
    const float* bh1  = (const float*)d_in[18];
    float* out = (float*)d_out;

    const int tot = W8_WORDS + WT_WORDS + 768;
    prepack_kernel<<<(tot + 255) / 256, 256>>>(Wm0, Wf10, Wf20, Wh0, Wm1,
                                               Wf11, Wf21, Wh1);
    egbrnn_main<<<NCTAS, NTHREADS>>>(x, targ, c0, bm0, bm1, bf10, bf11,
                                     bf20, bf21, bh0, bh1, out);
}

// round 16
// speedup vs baseline: 1.9070x; 1.9070x over previous
#include <cuda_runtime.h>
#include <cuda_bf16.h>

#define MCTA 16
#define NCTAS 128
#define NTHREADS 512
#define NWARPS 16
#define T_STEPS 128
#define KSTEPS 17
#define ACT_STRIDE 280   // bf16 elems per row (conflict-free ldmatrix)

// Packed weights, fragment order. Tile map (16 warps):
//   T in [0,32):    GEMM1 (Wm0), warp w owns T = 2w, 2w+1 (N cols [16w,16w+16))
//   T in [32,160):  per-warp P3 block: q=T-32, w=q/8, j=q%8
//                   j<6  -> GEMM2 tile tg=(6w+j)  (Wf10|Wf20|Wh0, n2=8*tg)
//                   j>=6 -> GEMM3 (Wm1) n-tile 2w+(j-6)
__device__ uint2 g_Wpk[160 * 17 * 32];
__device__ float4 g_smallW4[768];

// ---------------------------------------------------------------------------
// Activation column layout (padded K = 272):
//   0..255: c (actA) / cu (actB)   256..257: meas/60 (actB only; actA zero)
//   258..261: s/60 (both buffers)  262..271: 0
// Row remap: type0 (Wm0,Wf10,Wf20;fin260): k<256->k, 258..261->k-2 (m2 cols=0)
//            type1 (Wh0;fin262): k<256->k, 256,257->k+4, 258..261->k-2
//            type2 (Wm1;fin262): identity
// ---------------------------------------------------------------------------
__global__ void prepack_kernel(
    const float* __restrict__ Wm0, const float* __restrict__ Wf10,
    const float* __restrict__ Wf20, const float* __restrict__ Wh0,
    const float* __restrict__ Wm1, const float* __restrict__ Wf11,
    const float* __restrict__ Wf21, const float* __restrict__ Wh1)
{
    const int total_u32 = 160 * 17 * 32 * 2;
    int idx = blockIdx.x * blockDim.x + threadIdx.x;
    if (idx < total_u32) {
        int r    = idx & 1;
        int lane = (idx >> 1) & 31;
        int tk   = idx >> 6;          // tile*17 + ks
        int ks   = tk % 17;
        int tile = tk / 17;
        int kk = ks * 16 + (lane & 3) * 2 + r * 8;
        const float* W; int type; int ncol;
        if (tile < 32) {
            W = Wm0; type = 0; ncol = tile * 8 + (lane >> 2);
        } else {
            int q = tile - 32, wq = q >> 3, j = q & 7;
            if (j < 6) {
                int n2 = (wq * 6 + j) * 8 + (lane >> 2);
                if (n2 < 256)      { W = Wf10; type = 0; ncol = n2; }
                else if (n2 < 512) { W = Wf20; type = 0; ncol = n2 - 256; }
                else               { W = Wh0;  type = 1; ncol = n2 - 512; }
            } else {
                W = Wm1; type = 2; ncol = (wq * 2 + (j - 6)) * 8 + (lane >> 2);
            }
        }
        auto srcrow = [&](int k) -> int {
            if (type == 0) return k < 256 ? k : ((k >= 258 && k < 262) ? k - 2 : -1);
            if (type == 1) return k < 256 ? k : (k < 258 ? k + 4 : (k < 262 ? k - 2 : -1));
            return k < 262 ? k : -1;
        };
        int s0 = srcrow(kk), s1 = srcrow(kk + 1);
        float v0 = (s0 >= 0) ? W[(size_t)s0 * 256 + ncol] : 0.f;
        float v1 = (s1 >= 0) ? W[(size_t)s1 * 256 + ncol] : 0.f;
        __nv_bfloat162 p;
        p.x = __float2bfloat16(v0);
        p.y = __float2bfloat16(v1);
        reinterpret_cast<unsigned*>(g_Wpk)[idx] = *reinterpret_cast<unsigned*>(&p);
    } else if (idx < total_u32 + 768) {
        int j = idx - total_u32;
        float4 v = make_float4(0.f, 0.f, 0.f, 0.f);
        if (j < 256)      { v.x = Wf11[j * 2];        v.y = Wf11[j * 2 + 1]; }
        else if (j < 512) { int q = j - 256;
                            v.x = Wf21[q * 4]; v.y = Wf21[q * 4 + 1];
                            v.z = Wf21[q * 4 + 2]; v.w = Wf21[q * 4 + 3]; }
        else              { int q = j - 512;
                            v.x = Wh1[q * 2];  v.y = Wh1[q * 2 + 1]; }
        g_smallW4[j] = v;
    }
}

// ---------------------------------------------------------------------------
__device__ __forceinline__ void mma16816(float* d, const unsigned* a, uint2 b) {
    asm volatile(
        "mma.sync.aligned.m16n8k16.row.col.f32.bf16.bf16.f32 "
        "{%0,%1,%2,%3}, {%4,%5,%6,%7}, {%8,%9}, {%0,%1,%2,%3};\n"
        : "+f"(d[0]), "+f"(d[1]), "+f"(d[2]), "+f"(d[3])
        : "r"(a[0]), "r"(a[1]), "r"(a[2]), "r"(a[3]), "r"(b.x), "r"(b.y));
}
__device__ __forceinline__ void ldmA(unsigned* a, unsigned addr) {
    asm volatile(
        "ldmatrix.sync.aligned.m8n8.x4.shared.b16 {%0,%1,%2,%3}, [%4];\n"
        : "=r"(a[0]), "=r"(a[1]), "=r"(a[2]), "=r"(a[3]) : "r"(addr));
}
__device__ __forceinline__ float tanha(float x) {
    float y; asm("tanh.approx.f32 %0, %1;" : "=f"(y) : "f"(x)); return y;
}
__device__ __forceinline__ unsigned packbf2(float a, float b) {
    __nv_bfloat162 h;
    h.x = __float2bfloat16(a);
    h.y = __float2bfloat16(b);
    return *reinterpret_cast<unsigned*>(&h);
}

__device__ __forceinline__ void write_act_tanh(int ntile, int cbase, int row0,
        const float (&D)[4], const float* __restrict__ bias,
        __nv_bfloat16 (*actp)[ACT_STRIDE]) {
    int col = ntile * 8 + cbase;
    float bv0 = bias[col], bv1 = bias[col + 1];
    __nv_bfloat162 h0, h1;
    h0.x = __float2bfloat16(tanha(D[0] + bv0));
    h0.y = __float2bfloat16(tanha(D[1] + bv1));
    h1.x = __float2bfloat16(tanha(D[2] + bv0));
    h1.y = __float2bfloat16(tanha(D[3] + bv1));
    *reinterpret_cast<__nv_bfloat162*>(&actp[row0][col]) = h0;
    *reinterpret_cast<__nv_bfloat162*>(&actp[row0 + 8][col]) = h1;
}

__device__ __forceinline__ void g2_epilogue(int tg, int cbase,
        const float (&D)[4], const float* __restrict__ bias2s,
        const float4* __restrict__ smallWs, float (&o)[2][8]) {
    int col = tg * 8 + cbase;
    int seg = tg >> 5;  // 0: Wf11 (d), 1: Wf21 (pv), 2: Wh1 (hv)
    float bb0 = bias2s[col], bb1 = bias2s[col + 1];
    float4 w0 = smallWs[col];
    float4 w1 = smallWs[col + 1];
    int ob = (seg == 0) ? 0 : ((seg == 1) ? 2 : 6);
    float h0 = tanha(D[0] + bb0);
    float h1 = tanha(D[1] + bb1);
    float h2 = tanha(D[2] + bb0);
    float h3 = tanha(D[3] + bb1);
    o[0][ob + 0] += h0 * w0.x + h1 * w1.x;
    o[0][ob + 1] += h0 * w0.y + h1 * w1.y;
    o[1][ob + 0] += h2 * w0.x + h3 * w1.x;
    o[1][ob + 1] += h2 * w0.y + h3 * w1.y;
    if (seg == 1) {
        o[0][ob + 2] += h0 * w0.z + h1 * w1.z;
        o[0][ob + 3] += h0 * w0.w + h1 * w1.w;
        o[1][ob + 2] += h2 * w0.z + h3 * w1.z;
        o[1][ob + 3] += h2 * w0.w + h3 * w1.w;
    }
}

// ---------------------------------------------------------------------------
// Main persistent kernel: 128 CTAs x 512 threads, 16 batch rows per CTA.
// R13 champion + double-buffered activations -> 4 barriers/step.
//   Phase A: GEMM1(actA) -> cu into actB; m2 into actB tail.      [bar 1]
//   Phase B: GEMM2+GEMM3[0..15] from actB; partials.              [bar 2]
//   Phase C: Kalman (tid<16); su/60 -> both tails.                [bar 3]
//   Phase D: GEMM3 k16 (actB tail) -> c_new into actA.            [bar 4]
// ---------------------------------------------------------------------------
__global__ void __launch_bounds__(NTHREADS, 1) egbrnn_main(
    const float* __restrict__ x, const float* __restrict__ target,
    const float* __restrict__ c0,
    const float* __restrict__ bm0, const float* __restrict__ bm1,
    const float* __restrict__ bf10, const float* __restrict__ bf11,
    const float* __restrict__ bf20, const float* __restrict__ bf21,
    const float* __restrict__ bh0, const float* __restrict__ bh1,
    float* __restrict__ out)
{
    __shared__ __align__(16) __nv_bfloat16 actA[MCTA][ACT_STRIDE];
    __shared__ __align__(16) __nv_bfloat16 actB[MCTA][ACT_STRIDE];
    __shared__ float sS[MCTA][4];
    __shared__ float Pm[MCTA][16];
    __shared__ __align__(16) float part[NWARPS][MCTA][12];
    __shared__ float bm0s[256], bm1s[256], bias2s[768], biasSs[8];
    __shared__ __align__(16) float4 smallWs[768];

    const int tid = threadIdx.x;
    const int w = tid >> 5, lane = tid & 31;
    const int b0 = blockIdx.x * MCTA;
    const int row0 = lane >> 2;
    const int cbase = (lane & 3) * 2;

    // ---- one-time shared init ----
    if (tid < 256) { bm0s[tid] = bm0[tid]; bm1s[tid] = bm1[tid]; }
    for (int i = tid; i < 768; i += NTHREADS) {
        bias2s[i] = (i < 256) ? bf10[i] : (i < 512 ? bf20[i - 256] : bh0[i - 512]);
        smallWs[i] = g_smallW4[i];
    }
    if (tid < 8)
        biasSs[tid] = (tid < 2) ? bf11[tid] : (tid < 6 ? bf21[tid - 2] : bh1[tid - 6]);
    for (int i = tid; i < MCTA * 24; i += NTHREADS) {   // zero tails, both bufs
        int r = i / 24, c = 256 + i % 24;
        actA[r][c] = __float2bfloat16(0.f);
        actB[r][c] = __float2bfloat16(0.f);
    }
    for (int i = tid; i < MCTA * 256; i += NTHREADS) {  // actA cols 0..255 = c0
        int r = i >> 8, j = i & 255;
        actA[r][j] = __float2bfloat16(c0[(size_t)(b0 + r) * 256 + j]);
    }
    __syncthreads();
    if (tid < MCTA) {
        int r = tid;
        float4 tg = *reinterpret_cast<const float4*>(
            &target[((size_t)(b0 + r) * T_STEPS) * 4]);
        sS[r][0] = tg.x; sS[r][1] = tg.y; sS[r][2] = tg.z; sS[r][3] = tg.w;
#pragma unroll
        for (int i = 0; i < 16; i++) Pm[r][i] = (i % 5 == 0) ? 1.f : 0.f;
        unsigned a01 = packbf2(tg.x * (1.f / 60.f), tg.y * (1.f / 60.f));
        unsigned a23 = packbf2(tg.z * (1.f / 60.f), tg.w * (1.f / 60.f));
        *reinterpret_cast<unsigned*>(&actA[r][258]) = a01;  // s0/60
        *reinterpret_cast<unsigned*>(&actA[r][260]) = a23;
        *reinterpret_cast<unsigned*>(&actB[r][258]) = a01;
        *reinterpret_cast<unsigned*>(&actB[r][260]) = a23;
    }
    __syncthreads();

    const unsigned abA =
        (unsigned)__cvta_generic_to_shared(&actA[lane & 15][(lane >> 4) * 8]);
    const unsigned abB =
        (unsigned)__cvta_generic_to_shared(&actB[lane & 15][(lane >> 4) * 8]);
    const uint2* wG1 = g_Wpk + (2 * w) * KSTEPS * 32 + lane;
    const uint2* wP3 = g_Wpk + (32 + 8 * w) * KSTEPS * 32 + lane;

    // meas register prefetch (meaningful for tid<16 only)
    float2 xcur, xnxt;
    if (tid < MCTA)
        xcur = *reinterpret_cast<const float2*>(
            &x[((size_t)(b0 + tid)) * T_STEPS * 2]);

    for (int t = 0; t < T_STEPS; t++) {
        // ====== Phase A: GEMM1 (reads actA) -> cu into actB; m2; b3l ======
        float D1[2][4];
#pragma unroll
        for (int i = 0; i < 2; i++)
            D1[i][0] = D1[i][1] = D1[i][2] = D1[i][3] = 0.f;
        {
            unsigned a[2][4];
            uint2 b1[2][2];
            b1[0][0] = wG1[0];
            b1[1][0] = wG1[KSTEPS * 32];
            b1[0][1] = wG1[32];
            b1[1][1] = wG1[(KSTEPS + 1) * 32];
            ldmA(a[0], abA);
#pragma unroll
            for (int ks = 0; ks < KSTEPS; ks++) {
                if (ks + 1 < KSTEPS)
                    ldmA(a[(ks + 1) & 1], abA + (unsigned)(ks + 1) * 32u);
                mma16816(D1[0], a[ks & 1], b1[0][ks & 1]);
                mma16816(D1[1], a[ks & 1], b1[1][ks & 1]);
                if (ks + 2 < KSTEPS) {
                    b1[0][ks & 1] = wG1[(0 * KSTEPS + ks + 2) * 32];
                    b1[1][ks & 1] = wG1[(1 * KSTEPS + ks + 2) * 32];
                }
            }
        }
        write_act_tanh(2 * w,     cbase, row0, D1[0], bm0s, actB);
        write_act_tanh(2 * w + 1, cbase, row0, D1[1], bm0s, actB);
        uint2 b3l[2];
        b3l[0] = wP3[(6 * KSTEPS + 16) * 32];
        b3l[1] = wP3[(7 * KSTEPS + 16) * 32];
        if (tid < MCTA) {
            *reinterpret_cast<unsigned*>(&actB[tid][256]) =
                packbf2(xcur.x * (1.f / 60.f), xcur.y * (1.f / 60.f));
            int tn = (t + 1 < T_STEPS) ? t + 1 : t;
            xnxt = *reinterpret_cast<const float2*>(
                &x[(((size_t)(b0 + tid)) * T_STEPS + tn) * 2]);
        }
        __syncthreads();   // bar 1: actB (cu, m2) ready

        // ====== Phase B: GEMM2 (6 tiles) + GEMM3 ks0..15 (2) from actB ====
        float D2[8][4];
#pragma unroll
        for (int i = 0; i < 8; i++)
            D2[i][0] = D2[i][1] = D2[i][2] = D2[i][3] = 0.f;
        {
            unsigned a[2][4];
            uint2 b[8][2];
#pragma unroll
            for (int i = 0; i < 8; i++) {
                b[i][0] = wP3[(i * KSTEPS + 0) * 32];
                b[i][1] = wP3[(i * KSTEPS + 1) * 32];
            }
            ldmA(a[0], abB);
#pragma unroll
            for (int ks = 0; ks < KSTEPS; ks++) {
                if (ks + 1 < KSTEPS)
                    ldmA(a[(ks + 1) & 1], abB + (unsigned)(ks + 1) * 32u);
#pragma unroll
                for (int i = 0; i < 8; i++) {
                    if (i < 6 || ks < KSTEPS - 1)
                        mma16816(D2[i], a[ks & 1], b[i][ks & 1]);
                    if (ks + 2 < KSTEPS)
                        b[i][ks & 1] = wP3[(i * KSTEPS + ks + 2) * 32];
                }
            }
        }
        float o[2][8];
#pragma unroll
        for (int s = 0; s < 2; s++)
#pragma unroll
            for (int k = 0; k < 8; k++) o[s][k] = 0.f;
#pragma unroll
        for (int j = 0; j < 6; j++)
            g2_epilogue(6 * w + j, cbase, D2[j], bias2s, smallWs, o);
#pragma unroll
        for (int s = 0; s < 2; s++)
#pragma unroll
            for (int k = 0; k < 8; k++) {
                o[s][k] += __shfl_xor_sync(0xffffffffu, o[s][k], 1);
                o[s][k] += __shfl_xor_sync(0xffffffffu, o[s][k], 2);
            }
        if ((lane & 3) == 0) {
            float4* p0 = reinterpret_cast<float4*>(part[w][row0]);
            float4* p1 = reinterpret_cast<float4*>(part[w][row0 + 8]);
            p0[0] = make_float4(o[0][0], o[0][1], o[0][2], o[0][3]);
            p0[1] = make_float4(o[0][4], o[0][5], o[0][6], o[0][7]);
            p1[0] = make_float4(o[1][0], o[1][1], o[1][2], o[1][3]);
            p1[1] = make_float4(o[1][4], o[1][5], o[1][6], o[1][7]);
        }
        __syncthreads();   // bar 2: partials ready

        // ====== Phase C: per-row Kalman update (fp32), tid<16 =============
        if (tid < MCTA) {
            const int r = tid;
            float sm[8];
#pragma unroll
            for (int k = 0; k < 8; k++) sm[k] = biasSs[k];
#pragma unroll
            for (int ww = 0; ww < NWARPS; ww++) {
                const float4* pp = reinterpret_cast<const float4*>(part[ww][r]);
                float4 v0 = pp[0], v1 = pp[1];
                sm[0] += v0.x; sm[1] += v0.y; sm[2] += v0.z; sm[3] += v0.w;
                sm[4] += v1.x; sm[5] += v1.y; sm[6] += v1.z; sm[7] += v1.w;
            }
            const float d0 = sm[0], d1 = sm[1];
            const float pv[4] = {sm[2], sm[3], sm[4], sm[5]};
            const float hv0 = sm[6], hv1 = sm[7];
            float s0 = sS[r][0], s1 = sS[r][1], s2 = sS[r][2], s3 = sS[r][3];
            float sp[4];
            sp[0] = s0 + s2 + 0.5f * d0;
            sp[1] = s1 + s3 + 0.5f * d1;
            sp[2] = s2 + d0;
            sp[3] = s3 + d1;
            float P[4][4];
#pragma unroll
            for (int i = 0; i < 4; i++)
#pragma unroll
                for (int j = 0; j < 4; j++) P[i][j] = Pm[r][i * 4 + j];
            float FP[4][4], Pp[4][4];
#pragma unroll
            for (int j = 0; j < 4; j++) {
                FP[0][j] = P[0][j] + P[2][j];
                FP[1][j] = P[1][j] + P[3][j];
                FP[2][j] = P[2][j];
                FP[3][j] = P[3][j];
            }
#pragma unroll
            for (int i = 0; i < 4; i++) {
                Pp[i][0] = FP[i][0] + FP[i][2];
                Pp[i][1] = FP[i][1] + FP[i][3];
                Pp[i][2] = FP[i][2];
                Pp[i][3] = FP[i][3];
            }
#pragma unroll
            for (int i = 0; i < 4; i++)
#pragma unroll
                for (int j = 0; j < 4; j++) Pp[i][j] += pv[i] * pv[j];
#pragma unroll
            for (int i = 0; i < 4; i++) Pp[i][i] += 0.01f;
            float m0 = xcur.x, m1 = xcur.y;
            float in0 = m0 - sp[0], in1 = m1 - sp[1];
            float S00 = Pp[0][0] + hv0 * hv0 + 1.f;
            float S01 = Pp[0][1] + hv0 * hv1;
            float S10 = Pp[1][0] + hv1 * hv0;
            float S11 = Pp[1][1] + hv1 * hv1 + 1.f;
            float inv = 1.0f / (S00 * S11 - S01 * S10);
            float K[4][2], KS[4][2], su[4];
#pragma unroll
            for (int i = 0; i < 4; i++) {
                K[i][0] = (Pp[i][0] * S11 - Pp[i][1] * S10) * inv;
                K[i][1] = (Pp[i][1] * S00 - Pp[i][0] * S01) * inv;
                su[i] = sp[i] + K[i][0] * in0 + K[i][1] * in1;
                KS[i][0] = K[i][0] * S00 + K[i][1] * S10;
                KS[i][1] = K[i][0] * S01 + K[i][1] * S11;
            }
#pragma unroll
            for (int i = 0; i < 4; i++)
#pragma unroll
                for (int j = 0; j < 4; j++)
                    Pm[r][i * 4 + j] =
                        Pp[i][j] - KS[i][0] * K[j][0] - KS[i][1] * K[j][1];
            sS[r][0] = su[0]; sS[r][1] = su[1];
            sS[r][2] = su[2]; sS[r][3] = su[3];
            *reinterpret_cast<float4*>(
                &out[(((size_t)(b0 + r)) * T_STEPS + t) * 4]) =
                make_float4(su[0], su[1], su[2], su[3]);
            unsigned q01 = packbf2(su[0] * (1.f / 60.f), su[1] * (1.f / 60.f));
            unsigned q23 = packbf2(su[2] * (1.f / 60.f), su[3] * (1.f / 60.f));
            // su/60 to BOTH tails: actB for Phase D now, actA for next GEMM1
            *reinterpret_cast<unsigned*>(&actB[r][258]) = q01;
            *reinterpret_cast<unsigned*>(&actB[r][260]) = q23;
            *reinterpret_cast<unsigned*>(&actA[r][258]) = q01;
            *reinterpret_cast<unsigned*>(&actA[r][260]) = q23;
            xcur = xnxt;
        }
        __syncthreads();   // bar 3: su tails ready

        // ====== Phase D: GEMM3 final kstep (actB tail) -> c_new to actA ===
        {
            unsigned a0[4];
            ldmA(a0, abB + 16u * 32u);
            mma16816(D2[6], a0, b3l[0]);
            mma16816(D2[7], a0, b3l[1]);
        }
        write_act_tanh(2 * w,     cbase, row0, D2[6], bm1s, actA);
        write_act_tanh(2 * w + 1, cbase, row0, D2[7], bm1s, actA);
        __syncthreads();   // bar 4: actA (c_new) ready for next step
    }
}

// ---------------------------------------------------------------------------
extern "C" void kernel_launch(void* const* d_in, const int* in_sizes, int n_in,
                              void* d_out, int out_size)
{
    const float* x    = (const float*)d_in[0];
    const float* targ = (const float*)d_in[1];
    const float* c0   = (const float*)d_in[2];
    const float* Wm0  = (const float*)d_in[3];
    const float* bm0  = (const float*)d_in[4];
    const float* Wm1  = (const float*)d_in[5];
    const float* bm1  = (const float*)d_in[6];
    const float* Wf10 = (const float*)d_in[7];
    const float* bf10 = (const float*)d_in[8];
    const float* Wf11 = (const float*)d_in[9];
    const float* bf11 = (const float*)d_in[10];
    const float* Wf20 = (const float*)d_in[11];
    const float* bf20 = (const float*)d_in[12];
    const float* Wf21 = (const float*)d_in[13];
    const float* bf21 = (const float*)d_in[14];
    const float* Wh0  = (const float*)d_in[15];
    const float* bh0  = (const float*)d_in[16];
    const float* Wh1  = (const float*)d_in[17];
    const float* bh1  = (const float*)d_in[18];
    float* out = (float*)d_out;

    const int tot = 160 * 17 * 32 * 2 + 768;
    prepack_kernel<<<(tot + 255) / 256, 256>>>(Wm0, Wf10, Wf20, Wh0, Wm1,
                                               Wf11, Wf21, Wh1);
    egbrnn_main<<<NCTAS, NTHREADS>>>(x, targ, c0, bm0, bm1, bf10, bf11,
                                     bf20, bf21, bh0, bh1, out);
}

// round 17
// speedup vs baseline: 1.9110x; 1.0021x over previous
#include <cuda_runtime.h>
#include <cuda_bf16.h>

#define MCTA 16
#define NCTAS 128
#define NTHREADS 512
#define NWARPS 16
#define T_STEPS 128
#define KSTEPS 17
#define D1DEPTH 6        // P1 B-prefetch ring depth (fully unrolled)
#define ACT_STRIDE 280   // bf16 elems per row (conflict-free ldmatrix)

// Packed weights, fragment order. Tile map (16 warps):
//   T in [0,32):    GEMM1 (Wm0), warp w owns T = 2w, 2w+1 (N cols [16w,16w+16))
//   T in [32,160):  per-warp P3 block: q=T-32, w=q/8, j=q%8
//                   j<6  -> GEMM2 tile tg=(6w+j)  (Wf10|Wf20|Wh0, n2=8*tg)
//                   j>=6 -> GEMM3 (Wm1) n-tile 2w+(j-6)
__device__ uint2 g_Wpk[160 * 17 * 32];
__device__ float4 g_smallW4[768];

// ---------------------------------------------------------------------------
// Activation column layout (padded K = 272):
//   0..255: c / cu / c_new    256..257: meas/60    258..261: s/60   262..271: 0
// Row remap: type0 (Wm0,Wf10,Wf20;fin260): k<256->k, 258..261->k-2
//            type1 (Wh0;fin262): k<256->k, 256,257->k+4, 258..261->k-2
//            type2 (Wm1;fin262): identity
// ---------------------------------------------------------------------------
__global__ void prepack_kernel(
    const float* __restrict__ Wm0, const float* __restrict__ Wf10,
    const float* __restrict__ Wf20, const float* __restrict__ Wh0,
    const float* __restrict__ Wm1, const float* __restrict__ Wf11,
    const float* __restrict__ Wf21, const float* __restrict__ Wh1)
{
    const int total_u32 = 160 * 17 * 32 * 2;
    int idx = blockIdx.x * blockDim.x + threadIdx.x;
    if (idx < total_u32) {
        int r    = idx & 1;
        int lane = (idx >> 1) & 31;
        int tk   = idx >> 6;          // tile*17 + ks
        int ks   = tk % 17;
        int tile = tk / 17;
        int kk = ks * 16 + (lane & 3) * 2 + r * 8;
        const float* W; int type; int ncol;
        if (tile < 32) {
            W = Wm0; type = 0; ncol = tile * 8 + (lane >> 2);
        } else {
            int q = tile - 32, wq = q >> 3, j = q & 7;
            if (j < 6) {
                int n2 = (wq * 6 + j) * 8 + (lane >> 2);
                if (n2 < 256)      { W = Wf10; type = 0; ncol = n2; }
                else if (n2 < 512) { W = Wf20; type = 0; ncol = n2 - 256; }
                else               { W = Wh0;  type = 1; ncol = n2 - 512; }
            } else {
                W = Wm1; type = 2; ncol = (wq * 2 + (j - 6)) * 8 + (lane >> 2);
            }
        }
        auto srcrow = [&](int k) -> int {
            if (type == 0) return k < 256 ? k : ((k >= 258 && k < 262) ? k - 2 : -1);
            if (type == 1) return k < 256 ? k : (k < 258 ? k + 4 : (k < 262 ? k - 2 : -1));
            return k < 262 ? k : -1;
        };
        int s0 = srcrow(kk), s1 = srcrow(kk + 1);
        float v0 = (s0 >= 0) ? W[(size_t)s0 * 256 + ncol] : 0.f;
        float v1 = (s1 >= 0) ? W[(size_t)s1 * 256 + ncol] : 0.f;
        __nv_bfloat162 p;
        p.x = __float2bfloat16(v0);
        p.y = __float2bfloat16(v1);
        reinterpret_cast<unsigned*>(g_Wpk)[idx] = *reinterpret_cast<unsigned*>(&p);
    } else if (idx < total_u32 + 768) {
        int j = idx - total_u32;
        float4 v = make_float4(0.f, 0.f, 0.f, 0.f);
        if (j < 256)      { v.x = Wf11[j * 2];        v.y = Wf11[j * 2 + 1]; }
        else if (j < 512) { int q = j - 256;
                            v.x = Wf21[q * 4]; v.y = Wf21[q * 4 + 1];
                            v.z = Wf21[q * 4 + 2]; v.w = Wf21[q * 4 + 3]; }
        else              { int q = j - 512;
                            v.x = Wh1[q * 2];  v.y = Wh1[q * 2 + 1]; }
        g_smallW4[j] = v;
    }
}

// ---------------------------------------------------------------------------
__device__ __forceinline__ void mma16816(float* d, const unsigned* a, uint2 b) {
    asm volatile(
        "mma.sync.aligned.m16n8k16.row.col.f32.bf16.bf16.f32 "
        "{%0,%1,%2,%3}, {%4,%5,%6,%7}, {%8,%9}, {%0,%1,%2,%3};\n"
        : "+f"(d[0]), "+f"(d[1]), "+f"(d[2]), "+f"(d[3])
        : "r"(a[0]), "r"(a[1]), "r"(a[2]), "r"(a[3]), "r"(b.x), "r"(b.y));
}
__device__ __forceinline__ void ldmA(unsigned* a, unsigned addr) {
    asm volatile(
        "ldmatrix.sync.aligned.m8n8.x4.shared.b16 {%0,%1,%2,%3}, [%4];\n"
        : "=r"(a[0]), "=r"(a[1]), "=r"(a[2]), "=r"(a[3]) : "r"(addr));
}
__device__ __forceinline__ float tanha(float x) {
    float y; asm("tanh.approx.f32 %0, %1;" : "=f"(y) : "f"(x)); return y;
}
__device__ __forceinline__ unsigned packbf2(float a, float b) {
    __nv_bfloat162 h;
    h.x = __float2bfloat16(a);
    h.y = __float2bfloat16(b);
    return *reinterpret_cast<unsigned*>(&h);
}

__device__ __forceinline__ void write_act_tanh(int ntile, int cbase, int row0,
        const float (&D)[4], const float* __restrict__ bias,
        __nv_bfloat16 (*actp)[ACT_STRIDE]) {
    int col = ntile * 8 + cbase;
    float bv0 = bias[col], bv1 = bias[col + 1];
    __nv_bfloat162 h0, h1;
    h0.x = __float2bfloat16(tanha(D[0] + bv0));
    h0.y = __float2bfloat16(tanha(D[1] + bv1));
    h1.x = __float2bfloat16(tanha(D[2] + bv0));
    h1.y = __float2bfloat16(tanha(D[3] + bv1));
    *reinterpret_cast<__nv_bfloat162*>(&actp[row0][col]) = h0;
    *reinterpret_cast<__nv_bfloat162*>(&actp[row0 + 8][col]) = h1;
}

__device__ __forceinline__ void g2_epilogue(int tg, int cbase,
        const float (&D)[4], const float* __restrict__ bias2s,
        const float4* __restrict__ smallWs, float (&o)[2][8]) {
    int col = tg * 8 + cbase;
    int seg = tg >> 5;  // 0: Wf11 (d), 1: Wf21 (pv), 2: Wh1 (hv)
    float bb0 = bias2s[col], bb1 = bias2s[col + 1];
    float4 w0 = smallWs[col];
    float4 w1 = smallWs[col + 1];
    int ob = (seg == 0) ? 0 : ((seg == 1) ? 2 : 6);
    float h0 = tanha(D[0] + bb0);
    float h1 = tanha(D[1] + bb1);
    float h2 = tanha(D[2] + bb0);
    float h3 = tanha(D[3] + bb1);
    o[0][ob + 0] += h0 * w0.x + h1 * w1.x;
    o[0][ob + 1] += h0 * w0.y + h1 * w1.y;
    o[1][ob + 0] += h2 * w0.x + h3 * w1.x;
    o[1][ob + 1] += h2 * w0.y + h3 * w1.y;
    if (seg == 1) {
        o[0][ob + 2] += h0 * w0.z + h1 * w1.z;
        o[0][ob + 3] += h0 * w0.w + h1 * w1.w;
        o[1][ob + 2] += h2 * w0.z + h3 * w1.z;
        o[1][ob + 3] += h2 * w0.w + h3 * w1.w;
    }
}

// ---------------------------------------------------------------------------
// Main persistent kernel: 128 CTAs x 512 threads, 16 batch rows per CTA.
// R13 champion + deep (depth-6) B-prefetch in P1 only.
// ---------------------------------------------------------------------------
__global__ void __launch_bounds__(NTHREADS, 1) egbrnn_main(
    const float* __restrict__ x, const float* __restrict__ target,
    const float* __restrict__ c0,
    const float* __restrict__ bm0, const float* __restrict__ bm1,
    const float* __restrict__ bf10, const float* __restrict__ bf11,
    const float* __restrict__ bf20, const float* __restrict__ bf21,
    const float* __restrict__ bh0, const float* __restrict__ bh1,
    float* __restrict__ out)
{
    __shared__ __align__(16) __nv_bfloat16 act[MCTA][ACT_STRIDE];
    __shared__ float sS[MCTA][4];
    __shared__ float Pm[MCTA][16];
    __shared__ __align__(16) float part[NWARPS][MCTA][12];
    __shared__ float bm0s[256], bm1s[256], bias2s[768], biasSs[8];
    __shared__ __align__(16) float4 smallWs[768];

    const int tid = threadIdx.x;
    const int w = tid >> 5, lane = tid & 31;
    const int b0 = blockIdx.x * MCTA;
    const int row0 = lane >> 2;
    const int cbase = (lane & 3) * 2;

    // ---- one-time shared init ----
    if (tid < 256) { bm0s[tid] = bm0[tid]; bm1s[tid] = bm1[tid]; }
    for (int i = tid; i < 768; i += NTHREADS) {
        bias2s[i] = (i < 256) ? bf10[i] : (i < 512 ? bf20[i - 256] : bh0[i - 512]);
        smallWs[i] = g_smallW4[i];
    }
    if (tid < 8)
        biasSs[tid] = (tid < 2) ? bf11[tid] : (tid < 6 ? bf21[tid - 2] : bh1[tid - 6]);
    for (int i = tid; i < MCTA * 24; i += NTHREADS) {   // zero cols 256..279
        int r = i / 24, c = 256 + i % 24;
        act[r][c] = __float2bfloat16(0.f);
    }
    for (int i = tid; i < MCTA * 256; i += NTHREADS) {  // c = c0
        int r = i >> 8, j = i & 255;
        act[r][j] = __float2bfloat16(c0[(size_t)(b0 + r) * 256 + j]);
    }
    __syncthreads();
    if (tid < MCTA) {
        int r = tid;
        float4 tg = *reinterpret_cast<const float4*>(
            &target[((size_t)(b0 + r) * T_STEPS) * 4]);
        sS[r][0] = tg.x; sS[r][1] = tg.y; sS[r][2] = tg.z; sS[r][3] = tg.w;
#pragma unroll
        for (int i = 0; i < 16; i++) Pm[r][i] = (i % 5 == 0) ? 1.f : 0.f;
        *reinterpret_cast<unsigned*>(&act[r][258]) =
            packbf2(tg.x * (1.f / 60.f), tg.y * (1.f / 60.f));
        *reinterpret_cast<unsigned*>(&act[r][260]) =
            packbf2(tg.z * (1.f / 60.f), tg.w * (1.f / 60.f));
    }
    __syncthreads();

    const unsigned ab0 =
        (unsigned)__cvta_generic_to_shared(&act[lane & 15][(lane >> 4) * 8]);
    const uint2* wG1 = g_Wpk + (2 * w) * KSTEPS * 32 + lane;
    const uint2* wP3 = g_Wpk + (32 + 8 * w) * KSTEPS * 32 + lane;

    // meas register prefetch (meaningful for tid<16 only)
    float2 xcur, xnxt;
    if (tid < MCTA)
        xcur = *reinterpret_cast<const float2*>(
            &x[((size_t)(b0 + tid)) * T_STEPS * 2]);

    for (int t = 0; t < T_STEPS; t++) {
        // ---- P1: GEMM1 (cu preactivation), 2 tiles/warp, DEPTH-6 ring ----
        float D1[2][4];
#pragma unroll
        for (int i = 0; i < 2; i++)
            D1[i][0] = D1[i][1] = D1[i][2] = D1[i][3] = 0.f;
        {
            unsigned a[2][4];
            uint2 b1[2][D1DEPTH];
#pragma unroll
            for (int d = 0; d < D1DEPTH; d++) {
                b1[0][d] = wG1[(0 * KSTEPS + d) * 32];
                b1[1][d] = wG1[(1 * KSTEPS + d) * 32];
            }
            ldmA(a[0], ab0);
#pragma unroll
            for (int ks = 0; ks < KSTEPS; ks++) {
                if (ks + 1 < KSTEPS)
                    ldmA(a[(ks + 1) & 1], ab0 + (unsigned)(ks + 1) * 32u);
                mma16816(D1[0], a[ks & 1], b1[0][ks % D1DEPTH]);
                mma16816(D1[1], a[ks & 1], b1[1][ks % D1DEPTH]);
                if (ks + D1DEPTH < KSTEPS) {
                    b1[0][ks % D1DEPTH] = wG1[(0 * KSTEPS + ks + D1DEPTH) * 32];
                    b1[1][ks % D1DEPTH] = wG1[(1 * KSTEPS + ks + D1DEPTH) * 32];
                }
            }
        }
        __syncthreads();

        // ---- P2: write cu over c; m2 from reg; b3l loads; next-meas load --
        write_act_tanh(2 * w,     cbase, row0, D1[0], bm0s, act);
        write_act_tanh(2 * w + 1, cbase, row0, D1[1], bm0s, act);
        uint2 b3l[2];
        b3l[0] = wP3[(6 * KSTEPS + 16) * 32];
        b3l[1] = wP3[(7 * KSTEPS + 16) * 32];
        if (tid < MCTA) {
            *reinterpret_cast<unsigned*>(&act[tid][256]) =
                packbf2(xcur.x * (1.f / 60.f), xcur.y * (1.f / 60.f));
            int tn = (t + 1 < T_STEPS) ? t + 1 : t;
            xnxt = *reinterpret_cast<const float2*>(
                &x[(((size_t)(b0 + tid)) * T_STEPS + tn) * 2]);
        }
        __syncthreads();

        // ---- P3: fused GEMM2 (6 tiles) + GEMM3 ks0..15 (2 tiles) ----
        float D2[8][4];
#pragma unroll
        for (int i = 0; i < 8; i++)
            D2[i][0] = D2[i][1] = D2[i][2] = D2[i][3] = 0.f;
        {
            unsigned a[2][4];
            uint2 b[8][2];
#pragma unroll
            for (int i = 0; i < 8; i++) {
                b[i][0] = wP3[(i * KSTEPS + 0) * 32];
                b[i][1] = wP3[(i * KSTEPS + 1) * 32];
            }
            ldmA(a[0], ab0);
#pragma unroll
            for (int ks = 0; ks < KSTEPS; ks++) {
                if (ks + 1 < KSTEPS)
                    ldmA(a[(ks + 1) & 1], ab0 + (unsigned)(ks + 1) * 32u);
#pragma unroll
                for (int i = 0; i < 8; i++) {
                    if (i < 6 || ks < KSTEPS - 1)
                        mma16816(D2[i], a[ks & 1], b[i][ks & 1]);
                    if (ks + 2 < KSTEPS)
                        b[i][ks & 1] = wP3[(i * KSTEPS + ks + 2) * 32];
                }
            }
        }
        float o[2][8];
#pragma unroll
        for (int s = 0; s < 2; s++)
#pragma unroll
            for (int k = 0; k < 8; k++) o[s][k] = 0.f;
#pragma unroll
        for (int j = 0; j < 6; j++)
            g2_epilogue(6 * w + j, cbase, D2[j], bias2s, smallWs, o);
#pragma unroll
        for (int s = 0; s < 2; s++)
#pragma unroll
            for (int k = 0; k < 8; k++) {
                o[s][k] += __shfl_xor_sync(0xffffffffu, o[s][k], 1);
                o[s][k] += __shfl_xor_sync(0xffffffffu, o[s][k], 2);
            }
        if ((lane & 3) == 0) {
            float4* p0 = reinterpret_cast<float4*>(part[w][row0]);
            float4* p1 = reinterpret_cast<float4*>(part[w][row0 + 8]);
            p0[0] = make_float4(o[0][0], o[0][1], o[0][2], o[0][3]);
            p0[1] = make_float4(o[0][4], o[0][5], o[0][6], o[0][7]);
            p1[0] = make_float4(o[1][0], o[1][1], o[1][2], o[1][3]);
            p1[1] = make_float4(o[1][4], o[1][5], o[1][6], o[1][7]);
        }
        __syncthreads();

        // ---- P4: per-row Kalman update (fp32), tid<16, float4 reduce ----
        if (tid < MCTA) {
            const int r = tid;
            float sm[8];
#pragma unroll
            for (int k = 0; k < 8; k++) sm[k] = biasSs[k];
#pragma unroll
            for (int ww = 0; ww < NWARPS; ww++) {
                const float4* pp = reinterpret_cast<const float4*>(part[ww][r]);
                float4 v0 = pp[0], v1 = pp[1];
                sm[0] += v0.x; sm[1] += v0.y; sm[2] += v0.z; sm[3] += v0.w;
                sm[4] += v1.x; sm[5] += v1.y; sm[6] += v1.z; sm[7] += v1.w;
            }
            const float d0 = sm[0], d1 = sm[1];
            const float pv[4] = {sm[2], sm[3], sm[4], sm[5]};
            const float hv0 = sm[6], hv1 = sm[7];
            float s0 = sS[r][0], s1 = sS[r][1], s2 = sS[r][2], s3 = sS[r][3];
            float sp[4];
            sp[0] = s0 + s2 + 0.5f * d0;
            sp[1] = s1 + s3 + 0.5f * d1;
            sp[2] = s2 + d0;
            sp[3] = s3 + d1;
            float P[4][4];
#pragma unroll
            for (int i = 0; i < 4; i++)
#pragma unroll
                for (int j = 0; j < 4; j++) P[i][j] = Pm[r][i * 4 + j];
            float FP[4][4], Pp[4][4];
#pragma unroll
            for (int j = 0; j < 4; j++) {
                FP[0][j] = P[0][j] + P[2][j];
                FP[1][j] = P[1][j] + P[3][j];
                FP[2][j] = P[2][j];
                FP[3][j] = P[3][j];
            }
#pragma unroll
            for (int i = 0; i < 4; i++) {
                Pp[i][0] = FP[i][0] + FP[i][2];
                Pp[i][1] = FP[i][1] + FP[i][3];
                Pp[i][2] = FP[i][2];
                Pp[i][3] = FP[i][3];
            }
#pragma unroll
            for (int i = 0; i < 4; i++)
#pragma unroll
                for (int j = 0; j < 4; j++) Pp[i][j] += pv[i] * pv[j];
#pragma unroll
            for (int i = 0; i < 4; i++) Pp[i][i] += 0.01f;
            float m0 = xcur.x, m1 = xcur.y;
            float in0 = m0 - sp[0], in1 = m1 - sp[1];
            float S00 = Pp[0][0] + hv0 * hv0 + 1.f;
            float S01 = Pp[0][1] + hv0 * hv1;
            float S10 = Pp[1][0] + hv1 * hv0;
            float S11 = Pp[1][1] + hv1 * hv1 + 1.f;
            float inv = 1.0f / (S00 * S11 - S01 * S10);
            float K[4][2], KS[4][2], su[4];
#pragma unroll
            for (int i = 0; i < 4; i++) {
                K[i][0] = (Pp[i][0] * S11 - Pp[i][1] * S10) * inv;
                K[i][1] = (Pp[i][1] * S00 - Pp[i][0] * S01) * inv;
                su[i] = sp[i] + K[i][0] * in0 + K[i][1] * in1;
                KS[i][0] = K[i][0] * S00 + K[i][1] * S10;
                KS[i][1] = K[i][0] * S01 + K[i][1] * S11;
            }
#pragma unroll
            for (int i = 0; i < 4; i++)
#pragma unroll
                for (int j = 0; j < 4; j++)
                    Pm[r][i * 4 + j] =
                        Pp[i][j] - KS[i][0] * K[j][0] - KS[i][1] * K[j][1];
            sS[r][0] = su[0]; sS[r][1] = su[1];
            sS[r][2] = su[2]; sS[r][3] = su[3];
            *reinterpret_cast<float4*>(
                &out[(((size_t)(b0 + r)) * T_STEPS + t) * 4]) =
                make_float4(su[0], su[1], su[2], su[3]);
            *reinterpret_cast<unsigned*>(&act[r][258]) =
                packbf2(su[0] * (1.f / 60.f), su[1] * (1.f / 60.f));
            *reinterpret_cast<unsigned*>(&act[r][260]) =
                packbf2(su[2] * (1.f / 60.f), su[3] * (1.f / 60.f));
            xcur = xnxt;
        }
        __syncthreads();

        // ---- P5: GEMM3 final kstep (reads tail cols 256..271) + c_new.
        //      Reads only cols 256..271, writes only cols 0..255: disjoint. ----
        {
            unsigned a0[4];
            ldmA(a0, ab0 + 16u * 32u);
            mma16816(D2[6], a0, b3l[0]);
            mma16816(D2[7], a0, b3l[1]);
        }
        write_act_tanh(2 * w,     cbase, row0, D2[6], bm1s, act);
        write_act_tanh(2 * w + 1, cbase, row0, D2[7], bm1s, act);
        __syncthreads();
    }
}

// ---------------------------------------------------------------------------
extern "C" void kernel_launch(void* const* d_in, const int* in_sizes, int n_in,
                              void* d_out, int out_size)
{
    const float* x    = (const float*)d_in[0];
    const float* targ = (const float*)d_in[1];
    const float* c0   = (const float*)d_in[2];
    const float* Wm0  = (const float*)d_in[3];
    const float* bm0  = (const float*)d_in[4];
    const float* Wm1  = (const float*)d_in[5];
    const float* bm1  = (const float*)d_in[6];
    const float* Wf10 = (const float*)d_in[7];
    const float* bf10 = (const float*)d_in[8];
    const float* Wf11 = (const float*)d_in[9];
    const float* bf11 = (const float*)d_in[10];
    const float* Wf20 = (const float*)d_in[11];
    const float* bf20 = (const float*)d_in[12];
    const float* Wf21 = (const float*)d_in[13];
    const float* bf21 = (const float*)d_in[14];
    const float* Wh0  = (const float*)d_in[15];
    const float* bh0  = (const float*)d_in[16];
    const float* Wh1  = (const float*)d_in[17];
    const float* bh1  = (const float*)d_in[18];
    float* out = (float*)d_out;

    const int tot = 160 * 17 * 32 * 2 + 768;
    prepack_kernel<<<(tot + 255) / 256, 256>>>(Wm0, Wf10, Wf20, Wh0, Wm1,
                                               Wf11, Wf21, Wh1);
    egbrnn_main<<<NCTAS, NTHREADS>>>(x, targ, c0, bm0, bm1, bf10, bf11,
                                     bf20, bf21, bh0, bh1, out);
}